// round 3
// baseline (speedup 1.0000x reference)
#include <cuda_runtime.h>
#include <cuda_bf16.h>

#define FULLMASK 0xffffffffu

// One warp per 32x32 patch, lane = column.
// Per-warp per-lane private histograms hist[bin][lane]: bank == lane, conflict-free, no atomics.
// Per-pixel math replicates the JAX/XLA fp32 dataflow literally:
//   - gx, gy unscaled (conv products are exact: weights are powers of two)
//   - libdevice atan2f (XLA:GPU lowers arctan2 to __nv_atan2f)
//   - mag = sqrt((gx*gx + gy*gy) + 1e-8) with separate roundings (no fma contraction)
//   - o_big = ((ori + 2pi) + pi) * 36 / 2pi, each step rounded in f32 (__fdiv_rn)
// All controllable ops use explicitly-rounded intrinsics (fast-math-proof).

__global__ void __launch_bounds__(256)
pdgo_kernel(const float* __restrict__ patches, float* __restrict__ out, int B)
{
    __shared__ float hist[8][36 * 32];
    __shared__ float sbins[8][36];

    const int warp = threadIdx.x >> 5;
    const int lane = threadIdx.x & 31;
    const int pIdx = blockIdx.x * 8 + warp;
    if (pIdx >= B) return;

    float* hw = hist[warp];

    #pragma unroll
    for (int b = 0; b < 36; ++b) hw[b * 32 + lane] = 0.0f;
    __syncwarp();

    const float* p = patches + (size_t)pIdx * 1024 + lane;

    auto body = [&](float pv, float cv, float nv) {
        // column sums (plain rounded adds; 2*cv is exact)
        float t  = __fadd_rn(__fadd_rn(__fmul_rn(2.0f, cv), pv), nv);
        float dd = __fsub_rn(nv, pv);
        float tl = __shfl_up_sync(FULLMASK, t, 1);    // lane0 keeps own -> edge pad
        float tr = __shfl_down_sync(FULLMASK, t, 1);  // lane31 keeps own -> edge pad
        float dl = __shfl_up_sync(FULLMASK, dd, 1);
        float dr = __shfl_down_sync(FULLMASK, dd, 1);
        float ux = __fsub_rn(tr, tl);
        float uy = __fadd_rn(__fadd_rn(__fmul_rn(2.0f, dd), dl), dr);
        float gx = __fmul_rn(0.125f, ux);   // exact scaling
        float gy = __fmul_rn(0.125f, uy);   // exact scaling

        float xs  = __fadd_rn(gx, 1e-8f);
        float m2  = __fadd_rn(__fadd_rn(__fmul_rn(gx, gx), __fmul_rn(gy, gy)), 1e-8f);
        float mag = __fsqrt_rn(m2);

        float ori = atan2f(gy, xs);                              // libdevice __nv_atan2f
        float t1  = __fadd_rn(ori, 6.28318530717958647692f);     // ori + 2*pi
        float t2  = __fadd_rn(t1, 3.14159265358979323846f);      // ... + pi
        float t3  = __fmul_rn(36.0f, t2);
        float ob  = __fdiv_rn(t3, 6.28318530717958647692f);      // o_big in (36, 72]
        float fb  = floorf(ob);
        float w1f = __fsub_rn(ob, fb);

        int ib = (int)fb - 36;
        if (ib >= 36) ib -= 36;   // ob == 72 exactly -> bin 0
        if (ib < 0)   ib = 0;     // safety
        int ib1 = ib + 1; if (ib1 == 36) ib1 = 0;

        float w0v = __fmul_rn(__fsub_rn(1.0f, w1f), mag);
        float w1v = __fmul_rn(w1f, mag);
        hw[ib  * 32 + lane] += w0v;
        hw[ib1 * 32 + lane] += w1v;
    };

    float curr = __ldcs(p);       // row 0
    float prev = curr;            // edge pad: row -1 == row 0

    #pragma unroll 4
    for (int r = 0; r < 31; ++r) {
        float nxt = __ldcs(p + (r + 1) * 32);
        body(prev, curr, nxt);
        prev = curr; curr = nxt;
    }
    body(prev, curr, curr);       // row 31: next clamps to row 31
    __syncwarp();

    // Reduce 32 lane-private histograms per bin. Bank-rotated reads: no conflicts.
    float s0 = 0.0f, s1 = 0.0f;
    const int b2 = lane + 32;
    #pragma unroll
    for (int k = 0; k < 32; ++k) {
        int l = (lane + k) & 31;
        s0 = __fadd_rn(s0, hw[lane * 32 + l]);
        if (lane < 4) s1 = __fadd_rn(s1, hw[b2 * 32 + l]);
    }
    sbins[warp][lane] = s0;
    if (lane < 4) sbins[warp][b2] = s1;
    __syncwarp();

    const float* sb = sbins[warp];
    // sm[b] = (0.33*h[b-1] + 0.34*h[b]) + 0.33*h[b+1]  (left-to-right, no fma)
    int bm = (lane == 0) ? 35 : lane - 1;
    int bp = lane + 1;   // lane 31 -> bin 32, valid
    float sm0 = __fadd_rn(__fadd_rn(__fmul_rn(0.33f, sb[bm]),
                                    __fmul_rn(0.34f, sb[lane])),
                          __fmul_rn(0.33f, sb[bp]));
    float bv = sm0; int bi = lane;
    if (lane < 4) {
        int bb  = b2;
        int bm2 = bb - 1;
        int bp2 = (bb == 35) ? 0 : bb + 1;
        float sm1 = __fadd_rn(__fadd_rn(__fmul_rn(0.33f, sb[bm2]),
                                        __fmul_rn(0.34f, sb[bb])),
                              __fmul_rn(0.33f, sb[bp2]));
        if (sm1 > bv) { bv = sm1; bi = bb; }  // strict >: tie keeps lower index
    }
    #pragma unroll
    for (int o = 16; o > 0; o >>= 1) {
        float ov = __shfl_xor_sync(FULLMASK, bv, o);
        int   oi = __shfl_xor_sync(FULLMASK, bi, o);
        if (ov > bv || (ov == bv && oi < bi)) { bv = ov; bi = oi; }
    }
    if (lane == 0) {
        float fi = (float)bi;
        float v  = __fmul_rn(6.28318530717958647692f, fi);
        v = __fdiv_rn(v, 36.0f);
        out[pIdx] = -(__fadd_rn(v, -3.14159265358979323846f));
    }
}

extern "C" void kernel_launch(void* const* d_in, const int* in_sizes, int n_in,
                              void* d_out, int out_size)
{
    const float* patch = (const float*)d_in[0];
    float* out = (float*)d_out;
    int B = in_sizes[0] / 1024;      // 32*32 per patch
    int blocks = (B + 7) / 8;        // 8 warps (patches) per block
    pdgo_kernel<<<blocks, 256>>>(patch, out, B);
}

// round 4
// speedup vs baseline: 1.2918x; 1.2918x over previous
#include <cuda_runtime.h>
#include <cuda_bf16.h>

#define FULLMASK 0xffffffffu
typedef unsigned long long u64;

// Packed f32x2 helpers (sm_103a). add/mul.rn.f32x2 round each 32-bit half
// exactly like scalar add.rn/mul.rn -> bit-identical to the reference dataflow.
__device__ __forceinline__ u64 pk(float lo, float hi) {
    u64 r; asm("mov.b64 %0,{%1,%2};" : "=l"(r) : "f"(lo), "f"(hi)); return r;
}
__device__ __forceinline__ void upk(u64 v, float& lo, float& hi) {
    asm("mov.b64 {%0,%1},%2;" : "=f"(lo), "=f"(hi) : "l"(v));
}
__device__ __forceinline__ u64 f2add(u64 a, u64 b) {
    u64 r; asm("add.rn.f32x2 %0,%1,%2;" : "=l"(r) : "l"(a), "l"(b)); return r;
}
__device__ __forceinline__ u64 f2mul(u64 a, u64 b) {
    u64 r; asm("mul.rn.f32x2 %0,%1,%2;" : "=l"(r) : "l"(a), "l"(b)); return r;
}

// One warp per 32x32 patch, lane = column. Two rows processed per iteration
// with f32x2-packed arithmetic where rounding is provably identical.
// Per-warp per-lane private histograms hist[bin][lane]: bank == lane,
// conflict-free, no atomics; per-lane sequential add order preserved.
// Scalar tail (atan2f, div, floor, bins) replicates XLA's fp32 chain literally.

__global__ void __launch_bounds__(256, 6)
pdgo_kernel(const float* __restrict__ patches, float* __restrict__ out, int B)
{
    __shared__ float hist[8][36 * 32];   // 36 KB/block -> 6 blocks/SM

    const int warp = threadIdx.x >> 5;
    const int lane = threadIdx.x & 31;
    const int pIdx = blockIdx.x * 8 + warp;
    if (pIdx >= B) return;

    float* hw = hist[warp];

    #pragma unroll
    for (int b = 0; b < 36; ++b) hw[b * 32 + lane] = 0.0f;
    __syncwarp();

    const float* p = patches + (size_t)pIdx * 1024 + lane;

    const u64 EPS2   = pk(1e-8f, 1e-8f);
    const u64 TWOPI2 = pk(6.28318530717958647692f, 6.28318530717958647692f);
    const u64 PI2    = pk(3.14159265358979323846f, 3.14159265358979323846f);
    const u64 C36_2  = pk(36.0f, 36.0f);
    const u64 C125_2 = pk(0.125f, 0.125f);

    auto tail = [&](float t3, float mag) {
        float ob  = __fdiv_rn(t3, 6.28318530717958647692f);   // o_big in (36, 72]
        float fb  = floorf(ob);
        float w1f = __fsub_rn(ob, fb);
        int ib = (int)fb - 36;
        if (ib >= 36) ib -= 36;      // ob == 72 exactly -> bin 0
        if (ib < 0)   ib = 0;        // safety
        int ib1 = ib + 1; if (ib1 == 36) ib1 = 0;
        float w0v = __fmul_rn(__fsub_rn(1.0f, w1f), mag);
        float w1v = __fmul_rn(w1f, mag);
        hw[ib  * 32 + lane] += w0v;
        hw[ib1 * 32 + lane] += w1v;
    };

    // rows (r, r+1): lo half = row r, hi half = row r+1; window rm1..r2
    auto pair_body = [&](float rm1, float r0v, float r1v, float r2v) {
        u64 cv = pk(r0v, r1v);
        u64 pv = pk(rm1, r0v);
        u64 nv = pk(r1v, r2v);
        // t = (2*c + p) + n   (2*c == c+c, exact)
        u64 t2x = f2add(f2add(f2add(cv, cv), pv), nv);
        float ddl = __fsub_rn(r1v, rm1);
        float ddh = __fsub_rn(r2v, r0v);
        u64 dd2 = pk(ddl, ddh);

        u64 tl = __shfl_up_sync(FULLMASK, t2x, 1);    // lane0 keeps own -> edge pad
        u64 tr = __shfl_down_sync(FULLMASK, t2x, 1);  // lane31 keeps own -> edge pad
        u64 dl = __shfl_up_sync(FULLMASK, dd2, 1);
        u64 dr = __shfl_down_sync(FULLMASK, dd2, 1);

        float tll, tlh, trl, trh;
        upk(tl, tll, tlh); upk(tr, trl, trh);
        u64 ux2 = pk(__fsub_rn(trl, tll), __fsub_rn(trh, tlh));
        u64 uy2 = f2add(f2add(f2add(dd2, dd2), dl), dr);

        u64 gx2 = f2mul(C125_2, ux2);   // exact scaling
        u64 gy2 = f2mul(C125_2, uy2);   // exact scaling
        u64 xs2 = f2add(gx2, EPS2);
        u64 m22 = f2add(f2add(f2mul(gx2, gx2), f2mul(gy2, gy2)), EPS2);

        float m2l, m2h; upk(m22, m2l, m2h);
        float magl = __fsqrt_rn(m2l), magh = __fsqrt_rn(m2h);
        float gyl, gyh, xsl, xsh;
        upk(gy2, gyl, gyh); upk(xs2, xsl, xsh);
        float oril = atan2f(gyl, xsl);                 // libdevice __nv_atan2f
        float orih = atan2f(gyh, xsh);

        u64 ch = f2add(pk(oril, orih), TWOPI2);        // ori + 2*pi
        ch = f2add(ch, PI2);                           // ... + pi
        ch = f2mul(C36_2, ch);                         // * 36
        float t3l, t3h; upk(ch, t3l, t3h);
        tail(t3l, magl);
        tail(t3h, magh);
    };

    float r0v = __ldcs(p);        // row 0
    float rm1 = r0v;              // edge pad: row -1 == row 0

    #pragma unroll 2
    for (int k = 0; k < 15; ++k) {
        float r1v = __ldcs(p + (2 * k + 1) * 32);
        float r2v = __ldcs(p + (2 * k + 2) * 32);
        pair_body(rm1, r0v, r1v, r2v);
        rm1 = r1v; r0v = r2v;
    }
    {   // rows 30,31: row 32 clamps to row 31
        float r1v = __ldcs(p + 31 * 32);
        pair_body(rm1, r0v, r1v, r1v);
    }
    __syncwarp();

    // Reduce 32 lane-private histograms per bin. Bank-rotated reads: no conflicts.
    float s0 = 0.0f, s1 = 0.0f;
    const int b2 = lane + 32;
    #pragma unroll
    for (int k = 0; k < 32; ++k) {
        int l = (lane + k) & 31;
        s0 = __fadd_rn(s0, hw[lane * 32 + l]);
        if (lane < 4) s1 = __fadd_rn(s1, hw[b2 * 32 + l]);
    }
    __syncwarp();
    // Store the 36 reduced bins on a bank-safe diagonal inside hist (reuses smem):
    // idx(i) = i*32 + (i & 31)  ->  bank = i mod 32
    hw[lane * 32 + lane] = s0;
    if (lane < 4) hw[b2 * 32 + (b2 & 31)] = s1;
    __syncwarp();

    auto sbr = [&](int i) { return hw[i * 32 + (i & 31)]; };

    // sm[b] = (0.33*h[b-1] + 0.34*h[b]) + 0.33*h[b+1]  (no fma contraction)
    int bm = (lane == 0) ? 35 : lane - 1;
    int bp = lane + 1;   // lane 31 -> bin 32, valid
    float sm0 = __fadd_rn(__fadd_rn(__fmul_rn(0.33f, sbr(bm)),
                                    __fmul_rn(0.34f, sbr(lane))),
                          __fmul_rn(0.33f, sbr(bp)));
    float bv = sm0; int bi = lane;
    if (lane < 4) {
        int bb  = b2;
        int bm2 = bb - 1;
        int bp2 = (bb == 35) ? 0 : bb + 1;
        float sm1 = __fadd_rn(__fadd_rn(__fmul_rn(0.33f, sbr(bm2)),
                                        __fmul_rn(0.34f, sbr(bb))),
                              __fmul_rn(0.33f, sbr(bp2)));
        if (sm1 > bv) { bv = sm1; bi = bb; }  // strict >: tie keeps lower index
    }
    #pragma unroll
    for (int o = 16; o > 0; o >>= 1) {
        float ov = __shfl_xor_sync(FULLMASK, bv, o);
        int   oi = __shfl_xor_sync(FULLMASK, bi, o);
        if (ov > bv || (ov == bv && oi < bi)) { bv = ov; bi = oi; }
    }
    if (lane == 0) {
        float fi = (float)bi;
        float v  = __fmul_rn(6.28318530717958647692f, fi);
        v = __fdiv_rn(v, 36.0f);
        out[pIdx] = -(__fadd_rn(v, -3.14159265358979323846f));
    }
}

extern "C" void kernel_launch(void* const* d_in, const int* in_sizes, int n_in,
                              void* d_out, int out_size)
{
    // Ask for max shared-memory carveout so 6 blocks x 36KB fit per SM.
    cudaFuncSetAttribute(pdgo_kernel,
                         cudaFuncAttributePreferredSharedMemoryCarveout, 100);
    const float* patch = (const float*)d_in[0];
    float* out = (float*)d_out;
    int B = in_sizes[0] / 1024;      // 32*32 per patch
    int blocks = (B + 7) / 8;        // 8 warps (patches) per block
    pdgo_kernel<<<blocks, 256>>>(patch, out, B);
}

// round 5
// speedup vs baseline: 1.3888x; 1.0751x over previous
#include <cuda_runtime.h>
#include <cuda_bf16.h>

#define FULLMASK 0xffffffffu
typedef unsigned long long u64;

// Packed f32x2 helpers (sm_103a). add/mul/fma.rn.f32x2 round each 32-bit half
// exactly like the scalar .rn ops -> bit-identical to the reference dataflow.
__device__ __forceinline__ u64 pk(float lo, float hi) {
    u64 r; asm("mov.b64 %0,{%1,%2};" : "=l"(r) : "f"(lo), "f"(hi)); return r;
}
__device__ __forceinline__ void upk(u64 v, float& lo, float& hi) {
    asm("mov.b64 {%0,%1},%2;" : "=f"(lo), "=f"(hi) : "l"(v));
}
__device__ __forceinline__ u64 f2add(u64 a, u64 b) {
    u64 r; asm("add.rn.f32x2 %0,%1,%2;" : "=l"(r) : "l"(a), "l"(b)); return r;
}
__device__ __forceinline__ u64 f2mul(u64 a, u64 b) {
    u64 r; asm("mul.rn.f32x2 %0,%1,%2;" : "=l"(r) : "l"(a), "l"(b)); return r;
}
__device__ __forceinline__ u64 f2fma(u64 a, u64 b, u64 c) {
    u64 r; asm("fma.rn.f32x2 %0,%1,%2,%3;" : "=l"(r) : "l"(a), "l"(b), "l"(c)); return r;
}

// One warp per 32x32 patch, lane = column. Two rows per iteration, f32x2-packed.
// Division by the constant 2*pi uses the Markstein fma sequence (correctly
// rounded: y = rn(1/c); q0 = rn(x*y); r = fma(-c,q0,x); q = fma(r,y,q0)),
// replacing two full IEEE divisions with 3 packed ops.
// Per-warp per-lane private histograms hist[bin][lane]: bank == lane,
// conflict-free, no atomics; per-lane sequential add order preserved.

__global__ void __launch_bounds__(256, 6)
pdgo_kernel(const float* __restrict__ patches, float* __restrict__ out, int B)
{
    __shared__ float hist[8][36 * 32];   // 36 KB/block -> 6 blocks/SM

    const int warp = threadIdx.x >> 5;
    const int lane = threadIdx.x & 31;
    const int pIdx = blockIdx.x * 8 + warp;
    if (pIdx >= B) return;

    float* hw = hist[warp];

    #pragma unroll
    for (int b = 0; b < 36; ++b) hw[b * 32 + lane] = 0.0f;
    __syncwarp();

    const float* p = patches + (size_t)pIdx * 1024 + lane;

    constexpr float C2PI   = 6.28318530717958647692f;   // rounds to f32 2*pi (0x40C90FDB)
    constexpr float RCP2PI = 1.0f / C2PI;               // rn reciprocal, compile-time folded

    const u64 EPS2   = pk(1e-8f, 1e-8f);
    const u64 TWOPI2 = pk(C2PI, C2PI);
    const u64 PI2    = pk(3.14159265358979323846f, 3.14159265358979323846f);
    const u64 C36_2  = pk(36.0f, 36.0f);
    const u64 C125_2 = pk(0.125f, 0.125f);
    const u64 RCP2   = pk(RCP2PI, RCP2PI);
    const u64 NC2PI2 = pk(-C2PI, -C2PI);
    const u64 ONE2   = pk(1.0f, 1.0f);
    const u64 NONE2  = pk(-1.0f, -1.0f);

    auto binidx = [&](float fb) {
        int ib = (int)fb - 36;
        if (ib >= 36) ib -= 36;      // ob == 72 exactly -> bin 0
        if (ib < 0)   ib = 0;        // safety
        return ib;
    };

    // rows (r, r+1): lo half = row r, hi half = row r+1; window rm1..r2
    auto pair_body = [&](float rm1, float r0v, float r1v, float r2v) {
        u64 cv = pk(r0v, r1v);
        u64 pv = pk(rm1, r0v);
        u64 nv = pk(r1v, r2v);
        // t = (2*c + p) + n   (2*c == c+c, exact)
        u64 t2x = f2add(f2add(f2add(cv, cv), pv), nv);
        float ddl = __fsub_rn(r1v, rm1);
        float ddh = __fsub_rn(r2v, r0v);
        u64 dd2 = pk(ddl, ddh);

        u64 tl = __shfl_up_sync(FULLMASK, t2x, 1);    // lane0 keeps own -> edge pad
        u64 tr = __shfl_down_sync(FULLMASK, t2x, 1);  // lane31 keeps own -> edge pad
        u64 dl = __shfl_up_sync(FULLMASK, dd2, 1);
        u64 dr = __shfl_down_sync(FULLMASK, dd2, 1);

        float tll, tlh, trl, trh;
        upk(tl, tll, tlh); upk(tr, trl, trh);
        u64 ux2 = pk(__fsub_rn(trl, tll), __fsub_rn(trh, tlh));
        u64 uy2 = f2add(f2add(f2add(dd2, dd2), dl), dr);

        u64 gx2 = f2mul(C125_2, ux2);   // exact scaling
        u64 gy2 = f2mul(C125_2, uy2);   // exact scaling
        u64 xs2 = f2add(gx2, EPS2);
        u64 m22 = f2add(f2add(f2mul(gx2, gx2), f2mul(gy2, gy2)), EPS2);

        float m2l, m2h; upk(m22, m2l, m2h);
        float magl = __fsqrt_rn(m2l), magh = __fsqrt_rn(m2h);
        float gyl, gyh, xsl, xsh;
        upk(gy2, gyl, gyh); upk(xs2, xsl, xsh);
        float oril = atan2f(gyl, xsl);                 // libdevice __nv_atan2f
        float orih = atan2f(gyh, xsh);

        u64 ch = f2add(pk(oril, orih), TWOPI2);        // ori + 2*pi
        ch = f2add(ch, PI2);                           // ... + pi
        ch = f2mul(C36_2, ch);                         // t3 = 36 * t2

        // ob = rn(t3 / 2pi) via packed Markstein sequence
        u64 q0  = f2mul(ch, RCP2);
        u64 rr  = f2fma(NC2PI2, q0, ch);               // exact residual
        u64 ob2 = f2fma(rr, RCP2, q0);                 // correctly rounded quotient

        float obl, obh; upk(ob2, obl, obh);
        float fbl = floorf(obl), fbh = floorf(obh);
        float w1l = __fsub_rn(obl, fbl);
        float w1h = __fsub_rn(obh, fbh);

        // weights packed: (1 - w1f) via single-rounded fma, then two muls
        u64 w1f2  = pk(w1l, w1h);
        u64 mag2  = pk(magl, magh);
        u64 onem2 = f2fma(w1f2, NONE2, ONE2);          // rn(1 - w1f)
        u64 w0v2  = f2mul(onem2, mag2);
        u64 w1v2  = f2mul(w1f2, mag2);

        float w0l, w0h, w1vl, w1vh;
        upk(w0v2, w0l, w0h); upk(w1v2, w1vl, w1vh);

        int ibl = binidx(fbl);
        int ibl1 = ibl + 1; if (ibl1 == 36) ibl1 = 0;
        hw[ibl  * 32 + lane] += w0l;
        hw[ibl1 * 32 + lane] += w1vl;

        int ibh = binidx(fbh);
        int ibh1 = ibh + 1; if (ibh1 == 36) ibh1 = 0;
        hw[ibh  * 32 + lane] += w0h;
        hw[ibh1 * 32 + lane] += w1vh;
    };

    float r0v = __ldcs(p);        // row 0
    float rm1 = r0v;              // edge pad: row -1 == row 0

    #pragma unroll 2
    for (int k = 0; k < 15; ++k) {
        float r1v = __ldcs(p + (2 * k + 1) * 32);
        float r2v = __ldcs(p + (2 * k + 2) * 32);
        pair_body(rm1, r0v, r1v, r2v);
        rm1 = r1v; r0v = r2v;
    }
    {   // rows 30,31: row 32 clamps to row 31
        float r1v = __ldcs(p + 31 * 32);
        pair_body(rm1, r0v, r1v, r1v);
    }
    __syncwarp();

    // Reduce 32 lane-private histograms per bin. Bank-rotated reads: no conflicts.
    float s0 = 0.0f, s1 = 0.0f;
    const int b2 = lane + 32;
    #pragma unroll
    for (int k = 0; k < 32; ++k) {
        int l = (lane + k) & 31;
        s0 = __fadd_rn(s0, hw[lane * 32 + l]);
        if (lane < 4) s1 = __fadd_rn(s1, hw[b2 * 32 + l]);
    }
    __syncwarp();
    // Store the 36 reduced bins on a bank-safe diagonal inside hist (reuses smem):
    // idx(i) = i*32 + (i & 31)  ->  bank = i mod 32
    hw[lane * 32 + lane] = s0;
    if (lane < 4) hw[b2 * 32 + (b2 & 31)] = s1;
    __syncwarp();

    auto sbr = [&](int i) { return hw[i * 32 + (i & 31)]; };

    // sm[b] = (0.33*h[b-1] + 0.34*h[b]) + 0.33*h[b+1]  (no fma contraction)
    int bm = (lane == 0) ? 35 : lane - 1;
    int bp = lane + 1;   // lane 31 -> bin 32, valid
    float sm0 = __fadd_rn(__fadd_rn(__fmul_rn(0.33f, sbr(bm)),
                                    __fmul_rn(0.34f, sbr(lane))),
                          __fmul_rn(0.33f, sbr(bp)));
    float bv = sm0; int bi = lane;
    if (lane < 4) {
        int bb  = b2;
        int bm2 = bb - 1;
        int bp2 = (bb == 35) ? 0 : bb + 1;
        float sm1 = __fadd_rn(__fadd_rn(__fmul_rn(0.33f, sbr(bm2)),
                                        __fmul_rn(0.34f, sbr(bb))),
                              __fmul_rn(0.33f, sbr(bp2)));
        if (sm1 > bv) { bv = sm1; bi = bb; }  // strict >: tie keeps lower index
    }
    #pragma unroll
    for (int o = 16; o > 0; o >>= 1) {
        float ov = __shfl_xor_sync(FULLMASK, bv, o);
        int   oi = __shfl_xor_sync(FULLMASK, bi, o);
        if (ov > bv || (ov == bv && oi < bi)) { bv = ov; bi = oi; }
    }
    if (lane == 0) {
        float fi = (float)bi;
        float v  = __fmul_rn(6.28318530717958647692f, fi);
        v = __fdiv_rn(v, 36.0f);
        out[pIdx] = -(__fadd_rn(v, -3.14159265358979323846f));
    }
}

extern "C" void kernel_launch(void* const* d_in, const int* in_sizes, int n_in,
                              void* d_out, int out_size)
{
    // Ask for max shared-memory carveout so 6 blocks x 36KB fit per SM.
    cudaFuncSetAttribute(pdgo_kernel,
                         cudaFuncAttributePreferredSharedMemoryCarveout, 100);
    const float* patch = (const float*)d_in[0];
    float* out = (float*)d_out;
    int B = in_sizes[0] / 1024;      // 32*32 per patch
    int blocks = (B + 7) / 8;        // 8 warps (patches) per block
    pdgo_kernel<<<blocks, 256>>>(patch, out, B);
}

// round 6
// speedup vs baseline: 1.4076x; 1.0135x over previous
#include <cuda_runtime.h>
#include <cuda_bf16.h>

#define FULLMASK 0xffffffffu
typedef unsigned long long u64;

// Packed f32x2 helpers (sm_103a). add/mul/fma.rn.f32x2 round each 32-bit half
// exactly like the scalar .rn ops -> bit-identical to the reference dataflow.
__device__ __forceinline__ u64 pk(float lo, float hi) {
    u64 r; asm("mov.b64 %0,{%1,%2};" : "=l"(r) : "f"(lo), "f"(hi)); return r;
}
__device__ __forceinline__ void upk(u64 v, float& lo, float& hi) {
    asm("mov.b64 {%0,%1},%2;" : "=f"(lo), "=f"(hi) : "l"(v));
}
__device__ __forceinline__ u64 f2add(u64 a, u64 b) {
    u64 r; asm("add.rn.f32x2 %0,%1,%2;" : "=l"(r) : "l"(a), "l"(b)); return r;
}
__device__ __forceinline__ u64 f2mul(u64 a, u64 b) {
    u64 r; asm("mul.rn.f32x2 %0,%1,%2;" : "=l"(r) : "l"(a), "l"(b)); return r;
}
__device__ __forceinline__ u64 f2fma(u64 a, u64 b, u64 c) {
    u64 r; asm("fma.rn.f32x2 %0,%1,%2,%3;" : "=l"(r) : "l"(a), "l"(b), "l"(c)); return r;
}

// One warp per 32x32 patch, lane = column. Two rows per iteration, f32x2-packed.
// Works in the 8x-scaled gradient domain (exact power-of-2; EPS pre-scaled).
// o_big floor indexes a 39-row per-lane histogram directly (row = floor-35),
// reproducing the reference's %36 for the +/-1-ulp edge rows via aliases
// folded at reduce time. Division by 2*pi via packed Markstein fma sequence
// (correctly rounded). hist[row][lane]: bank == lane, conflict-free, no atomics.

__global__ void __launch_bounds__(128, 11)
pdgo_kernel(const float* __restrict__ patches, float* __restrict__ out, int B)
{
    __shared__ float hist[4][39 * 32];   // 19.9 KB/block -> 11 blocks/SM

    const int warp = threadIdx.x >> 5;
    const int lane = threadIdx.x & 31;
    const int pIdx = blockIdx.x * 4 + warp;
    if (pIdx >= B) return;

    float* hw = hist[warp];
    float* hl = hw + lane;

    #pragma unroll
    for (int b = 0; b < 39; ++b) hw[b * 32 + lane] = 0.0f;
    __syncwarp();

    const float* p = patches + (size_t)pIdx * 1024 + lane;

    constexpr float C2PI   = 6.28318530717958647692f;   // f32 2*pi (0x40C90FDB)
    constexpr float RCP2PI = 1.0f / C2PI;               // rn reciprocal, folded

    const u64 TWO2   = pk(2.0f, 2.0f);
    const u64 EPS8   = pk(8e-8f, 8e-8f);     // 8 * f32(1e-8), exact scaling
    const u64 EPS64  = pk(6.4e-7f, 6.4e-7f); // 64 * f32(1e-8), exact scaling
    const u64 TWOPI2 = pk(C2PI, C2PI);
    const u64 PI2    = pk(3.14159265358979323846f, 3.14159265358979323846f);
    const u64 C36_2  = pk(36.0f, 36.0f);
    const u64 RCP2   = pk(RCP2PI, RCP2PI);
    const u64 NC2PI2 = pk(-C2PI, -C2PI);
    const u64 ONE2   = pk(1.0f, 1.0f);
    const u64 NONE2  = pk(-1.0f, -1.0f);

    // rows (r, r+1): lo half = row r, hi half = row r+1; window rm1..r2
    auto pair_body = [&](float rm1, float r0v, float r1v, float r2v) {
        u64 cv = pk(r0v, r1v);
        u64 pv = pk(rm1, r0v);
        u64 nv = pk(r1v, r2v);
        // t = (2*c + p) + n ; rn(2c+p) == rn((c+c)+p) since 2c is exact
        u64 t2x = f2add(f2fma(TWO2, cv, pv), nv);
        float ddl = __fsub_rn(r1v, rm1);
        float ddh = __fsub_rn(r2v, r0v);
        u64 dd2 = pk(ddl, ddh);

        u64 tl = __shfl_up_sync(FULLMASK, t2x, 1);    // lane0 keeps own -> edge pad
        u64 tr = __shfl_down_sync(FULLMASK, t2x, 1);  // lane31 keeps own -> edge pad
        u64 dl = __shfl_up_sync(FULLMASK, dd2, 1);
        u64 dr = __shfl_down_sync(FULLMASK, dd2, 1);

        float tll, tlh, trl, trh;
        upk(tl, tll, tlh); upk(tr, trl, trh);
        u64 ux2 = pk(__fsub_rn(trl, tll), __fsub_rn(trh, tlh));   // 8*gx
        u64 uy2 = f2add(f2fma(TWO2, dd2, dl), dr);                // 8*gy

        u64 xs2 = f2add(ux2, EPS8);                               // 8*(gx+eps)
        u64 m22 = f2add(f2add(f2mul(ux2, ux2), f2mul(uy2, uy2)), EPS64);  // 64*m2

        float m2l, m2h; upk(m22, m2l, m2h);
        float magl = __fsqrt_rn(m2l), magh = __fsqrt_rn(m2h);     // 8*mag, exact
        float uyl, uyh, xsl, xsh;
        upk(uy2, uyl, uyh); upk(xs2, xsl, xsh);
        float oril = atan2f(uyl, xsl);   // == atan2f(gy, xs): scale-invariant
        float orih = atan2f(uyh, xsh);

        u64 ch = f2mul(C36_2, f2add(f2add(pk(oril, orih), TWOPI2), PI2)); // t3

        // ob = rn(t3 / 2pi) via packed Markstein sequence (correctly rounded)
        u64 q0  = f2mul(ch, RCP2);
        u64 rr  = f2fma(NC2PI2, q0, ch);               // exact residual
        u64 ob2 = f2fma(rr, RCP2, q0);

        float obl, obh; upk(ob2, obl, obh);
        float fbl = floorf(obl), fbh = floorf(obh);    // fb in [35, 72]
        u64 w1f2 = pk(__fsub_rn(obl, fbl), __fsub_rn(obh, fbh));
        u64 mag2 = pk(magl, magh);
        u64 onem = f2fma(w1f2, NONE2, ONE2);           // rn(1 - w1f)
        u64 w0v2 = f2mul(onem, mag2);
        u64 w1v2 = f2mul(w1f2, mag2);

        float w0l, w0h, w1vl, w1vh;
        upk(w0v2, w0l, w0h); upk(w1v2, w1vl, w1vh);

        // row = floor - 35 in [0, 37]; row+1 in [1, 38]; aliases folded later
        int rl = (int)fbl * 32 - 35 * 32;
        hl[rl]      += w0l;
        hl[rl + 32] += w1vl;
        int rh = (int)fbh * 32 - 35 * 32;
        hl[rh]      += w0h;
        hl[rh + 32] += w1vh;
    };

    float r0v = __ldcs(p);        // row 0
    float rm1 = r0v;              // edge pad: row -1 == row 0

    #pragma unroll 2
    for (int k = 0; k < 15; ++k) {
        float r1v = __ldcs(p + (2 * k + 1) * 32);
        float r2v = __ldcs(p + (2 * k + 2) * 32);
        pair_body(rm1, r0v, r1v, r2v);
        rm1 = r1v; r0v = r2v;
    }
    {   // rows 30,31: row 32 clamps to row 31
        float r1v = __ldcs(p + 31 * 32);
        pair_body(rm1, r0v, r1v, r1v);
    }
    __syncwarp();

    // Reduce 32 lane-private copies per row. Rotated reads: bank-conflict-free.
    // Row r corresponds to bin (r-1) mod 36; rows 0,37,38 alias bins 35,0,1.
    const int rowA = lane + 1;                              // rows 1..32 (bins 0..31)
    const int rowB = (lane < 6) ? (33 + lane) : 0;          // rows 33..38, 0 (lanes 0..6)
    float s0 = 0.0f, s1 = 0.0f;
    #pragma unroll
    for (int k = 0; k < 32; ++k) {
        int l = (lane + k) & 31;
        s0 = __fadd_rn(s0, hw[rowA * 32 + l]);
        if (lane < 7) s1 = __fadd_rn(s1, hw[rowB * 32 + l]);
    }
    __syncwarp();
    // Diagonal slots: slot i at hw[i*32 + (i & 31)]  (bank = i mod 32)
    hw[rowA * 32 + (rowA & 31)] = s0;                       // slots 1..32
    if (lane < 7) hw[rowB * 32 + (rowB & 31)] = s1;         // slots 33..38, 0
    __syncwarp();
    // Fold aliases (appended-last add order; ordering noise class is tolerated)
    if (lane == 0) hw[1 * 32 + 1]   = __fadd_rn(hw[1 * 32 + 1],   hw[37 * 32 + 5]); // bin 0
    if (lane == 1) hw[2 * 32 + 2]   = __fadd_rn(hw[2 * 32 + 2],   hw[38 * 32 + 6]); // bin 1
    if (lane == 2) hw[36 * 32 + 4]  = __fadd_rn(hw[36 * 32 + 4],  hw[0]);           // bin 35
    __syncwarp();

    auto hbin = [&](int b) { int s = b + 1; return hw[s * 32 + (s & 31)]; };

    // sm[b] = (0.33*h[b-1] + 0.34*h[b]) + 0.33*h[b+1]  (no fma contraction)
    int bm = (lane == 0) ? 35 : lane - 1;
    int bp = lane + 1;   // lane 31 -> bin 32, valid
    float sm0 = __fadd_rn(__fadd_rn(__fmul_rn(0.33f, hbin(bm)),
                                    __fmul_rn(0.34f, hbin(lane))),
                          __fmul_rn(0.33f, hbin(bp)));
    float bv = sm0; int bi = lane;
    if (lane < 4) {
        int bb  = 32 + lane;
        int bm2 = bb - 1;
        int bp2 = (bb == 35) ? 0 : bb + 1;
        float sm1 = __fadd_rn(__fadd_rn(__fmul_rn(0.33f, hbin(bm2)),
                                        __fmul_rn(0.34f, hbin(bb))),
                              __fmul_rn(0.33f, hbin(bp2)));
        if (sm1 > bv) { bv = sm1; bi = bb; }  // strict >: tie keeps lower index
    }
    #pragma unroll
    for (int o = 16; o > 0; o >>= 1) {
        float ov = __shfl_xor_sync(FULLMASK, bv, o);
        int   oi = __shfl_xor_sync(FULLMASK, bi, o);
        if (ov > bv || (ov == bv && oi < bi)) { bv = ov; bi = oi; }
    }
    if (lane == 0) {
        float fi = (float)bi;
        float v  = __fmul_rn(6.28318530717958647692f, fi);
        v = __fdiv_rn(v, 36.0f);
        out[pIdx] = -(__fadd_rn(v, -3.14159265358979323846f));
    }
}

extern "C" void kernel_launch(void* const* d_in, const int* in_sizes, int n_in,
                              void* d_out, int out_size)
{
    cudaFuncSetAttribute(pdgo_kernel,
                         cudaFuncAttributePreferredSharedMemoryCarveout, 100);
    const float* patch = (const float*)d_in[0];
    float* out = (float*)d_out;
    int B = in_sizes[0] / 1024;      // 32*32 per patch
    int blocks = (B + 3) / 4;        // 4 warps (patches) per 128-thread block
    pdgo_kernel<<<blocks, 128>>>(patch, out, B);
}